// round 1
// baseline (speedup 1.0000x reference)
#include <cuda_runtime.h>
#include <math.h>

// ---------------------------------------------------------------------------
// Problem: out[k] = sigmoid( concat(feature[a], feature[b]) @ W1 @ W2 @ W3 @ W4
//                            + (b1@W2@W3@W4 + b2@W3@W4 + b3@W4 + b4) )
// No activations between Linears -> collapse to a single affine form:
//   v4 = W4[:,0] (64), v3 = W3 v4 (512), v2 = W2 v3 (1024), v1 = W1 v2 (1802)
//   c  = b1.v2 + b2.v3 + b3.v4 + b4[0]
//   s1[e] = feature[e] . v1[0:901], s2[e] = feature[e] . v1[901:1802]
//   out[k] = sigmoid(s1[a] + s2[b] + c)
// ---------------------------------------------------------------------------

#define N_ENT 20000
#define D     901
#define B_TR  100000
#define B_TE  25000

__device__ float g_v3[512];
__device__ float g_v2[1024];
__device__ float g_v1[2 * D];      // 1802
__device__ float g_c;
__device__ float g_s[2 * N_ENT];   // interleaved: s1[e]=g_s[2e], s2[e]=g_s[2e+1]

// Warp-per-row matvec: out[r] = sum_j W[r*cols + j] * v[j]
// Double accumulation (tiny kernels; keeps the collapsed chain numerically tight).
__global__ void k_matvec(const float* __restrict__ W, const float* __restrict__ v,
                         float* __restrict__ out, int rows, int cols) {
    int warp = (blockIdx.x * blockDim.x + threadIdx.x) >> 5;
    int lane = threadIdx.x & 31;
    if (warp >= rows) return;
    const float* row = W + (size_t)warp * cols;
    double acc = 0.0;
    for (int j = lane; j < cols; j += 32)
        acc += (double)row[j] * (double)v[j];
    #pragma unroll
    for (int o = 16; o; o >>= 1)
        acc += __shfl_down_sync(0xffffffffu, acc, o);
    if (lane == 0) out[warp] = (float)acc;
}

// c = b1.v2 + b2.v3 + b3.v4 + b4[0]   (single block, 1024 threads)
__global__ void k_bias(const float* __restrict__ b1, const float* __restrict__ b2,
                       const float* __restrict__ b3, const float* __restrict__ b4,
                       const float* __restrict__ W4) {
    __shared__ double red[32];
    int t = threadIdx.x;
    double acc = 0.0;
    if (t < 1024) acc += (double)b1[t] * (double)g_v2[t];
    if (t < 512)  acc += (double)b2[t] * (double)g_v3[t];
    if (t < 64)   acc += (double)b3[t] * (double)W4[t];   // v4 == W4 (fout=1)
    #pragma unroll
    for (int o = 16; o; o >>= 1)
        acc += __shfl_down_sync(0xffffffffu, acc, o);
    if ((t & 31) == 0) red[t >> 5] = acc;
    __syncthreads();
    if (t == 0) {
        double s = 0.0;
        #pragma unroll
        for (int w = 0; w < 32; w++) s += red[w];
        g_c = (float)(s + (double)b4[0]);
    }
}

// Warp-per-entity: stream the 901-float feature row once, accumulate both half-dots.
__global__ void k_scores(const float* __restrict__ feat) {
    int warp = (blockIdx.x * blockDim.x + threadIdx.x) >> 5;
    int lane = threadIdx.x & 31;
    if (warp >= N_ENT) return;
    const float* row = feat + (size_t)warp * D;
    float s1 = 0.f, s2 = 0.f;
    for (int j = lane; j < D; j += 32) {
        float f = row[j];
        s1 = fmaf(f, g_v1[j], s1);
        s2 = fmaf(f, g_v1[D + j], s2);
    }
    #pragma unroll
    for (int o = 16; o; o >>= 1) {
        s1 += __shfl_down_sync(0xffffffffu, s1, o);
        s2 += __shfl_down_sync(0xffffffffu, s2, o);
    }
    if (lane == 0) {
        g_s[2 * warp]     = s1;
        g_s[2 * warp + 1] = s2;
    }
}

// Gather + sigmoid. Train pairs first (100000), then test (25000).
__global__ void k_out(const int* __restrict__ tr, const int* __restrict__ te,
                      float* __restrict__ out) {
    int k = blockIdx.x * blockDim.x + threadIdx.x;
    if (k >= B_TR + B_TE) return;
    int a, b;
    if (k < B_TR) { a = tr[2 * k];            b = tr[2 * k + 1]; }
    else          { int m = k - B_TR; a = te[2 * m]; b = te[2 * m + 1]; }
    float z = g_s[2 * a] + g_s[2 * b + 1] + g_c;
    out[k] = 1.0f / (1.0f + expf(-z));
}

extern "C" void kernel_launch(void* const* d_in, const int* in_sizes, int n_in,
                              void* d_out, int out_size) {
    const float* feature = (const float*)d_in[0];   // [20000, 901]
    const float* W1      = (const float*)d_in[1];   // [1802, 1024]
    const float* b1      = (const float*)d_in[2];   // [1024]
    const float* W2      = (const float*)d_in[3];   // [1024, 512]
    const float* b2      = (const float*)d_in[4];   // [512]
    const float* W3      = (const float*)d_in[5];   // [512, 64]
    const float* b3      = (const float*)d_in[6];   // [64]
    const float* W4      = (const float*)d_in[7];   // [64, 1]
    const float* b4      = (const float*)d_in[8];   // [1]
    const int*   tr      = (const int*)d_in[9];     // [100000, 2]
    const int*   te      = (const int*)d_in[10];    // [25000, 2]
    float*       out     = (float*)d_out;

    float *p_v3, *p_v2, *p_v1;
    cudaGetSymbolAddress((void**)&p_v3, g_v3);
    cudaGetSymbolAddress((void**)&p_v2, g_v2);
    cudaGetSymbolAddress((void**)&p_v1, g_v1);

    const int TPB = 256;               // 8 warps per block
    // v3 = W3 @ v4   (512 rows x 64 cols)
    k_matvec<<<(512 * 32 + TPB - 1) / TPB, TPB>>>(W3, W4, p_v3, 512, 64);
    // v2 = W2 @ v3   (1024 rows x 512 cols)
    k_matvec<<<(1024 * 32 + TPB - 1) / TPB, TPB>>>(W2, p_v3, p_v2, 1024, 512);
    // c  (needs v2, v3)
    k_bias<<<1, 1024>>>(b1, b2, b3, b4, W4);
    // v1 = W1 @ v2   (1802 rows x 1024 cols)
    k_matvec<<<(1802 * 32 + TPB - 1) / TPB, TPB>>>(W1, p_v2, p_v1, 1802, 1024);
    // per-entity scores (20000 warps)
    k_scores<<<(N_ENT * 32 + TPB - 1) / TPB, TPB>>>(feature);
    // final gather + sigmoid
    k_out<<<(B_TR + B_TE + TPB - 1) / TPB, TPB>>>(tr, te, out);
}

// round 2
// speedup vs baseline: 1.7477x; 1.7477x over previous
#include <cuda_runtime.h>
#include <math.h>

// ---------------------------------------------------------------------------
// out[k] = sigmoid( concat(feature[a], feature[b]) @ W1 @ W2 @ W3 @ W4 + c )
// No inter-layer activations -> collapse to one affine form:
//   v4 = W4[:,0] (64), v3 = W3 v4 (512), v2 = W2 v3 (1024), v1 = W1 v2 (1802)
//   c  = b1.v2 + b2.v3 + b3.v4 + b4[0]
//   s1[e] = feature[e] . v1[0:901], s2[e] = feature[e] . v1[901:1802]
//   out[k] = sigmoid(s1[a] + s2[b] + c)
// All fp32 (rel_err budget 1e-3; measured chain error ~1e-7).
// ---------------------------------------------------------------------------

#define N_ENT 20000
#define D     901
#define B_TR  100000
#define B_TE  25000

__device__ __align__(16) float g_v3[512];
__device__ __align__(16) float g_v2[1024];
__device__ __align__(16) float g_v1[2 * D + 2];   // 1802 (+pad)
__device__ float g_c;
__device__ __align__(16) float g_s[2 * N_ENT];    // s1[e]=g_s[2e], s2[e]=g_s[2e+1]

// Warp-per-row matvec, float4 loads: out[r] = sum_j W[r,j]*v[j]
__global__ void k_matvec(const float* __restrict__ W, const float* __restrict__ v,
                         float* __restrict__ out, int rows, int cols4) {
    int warp = (blockIdx.x * blockDim.x + threadIdx.x) >> 5;
    int lane = threadIdx.x & 31;
    if (warp >= rows) return;
    const float4* row = (const float4*)W + (size_t)warp * cols4;
    const float4* v4  = (const float4*)v;
    float acc = 0.f;
    #pragma unroll 4
    for (int j = lane; j < cols4; j += 32) {
        float4 a = row[j];
        float4 b = v4[j];
        acc = fmaf(a.x, b.x, acc);
        acc = fmaf(a.y, b.y, acc);
        acc = fmaf(a.z, b.z, acc);
        acc = fmaf(a.w, b.w, acc);
    }
    #pragma unroll
    for (int o = 16; o; o >>= 1)
        acc += __shfl_down_sync(0xffffffffu, acc, o);
    if (lane == 0) out[warp] = acc;
}

// v1 = W1 @ v2 (1802 x 1024), with the LAST block computing
// c = b1.v2 + b2.v3 + b3.v4 + b4[0]  (fused to save a launch).
__global__ void k_v1_bias(const float* __restrict__ W1,
                          const float* __restrict__ b1, const float* __restrict__ b2,
                          const float* __restrict__ b3, const float* __restrict__ b4,
                          const float* __restrict__ W4) {
    if (blockIdx.x == gridDim.x - 1) {
        // bias-constant reduction with 256 threads
        __shared__ float red[8];
        int t = threadIdx.x;
        float acc = 0.f;
        #pragma unroll
        for (int j = t; j < 1024; j += 256) acc = fmaf(b1[j], g_v2[j], acc);
        #pragma unroll
        for (int j = t; j < 512; j += 256)  acc = fmaf(b2[j], g_v3[j], acc);
        if (t < 64)                         acc = fmaf(b3[t], W4[t], acc);
        #pragma unroll
        for (int o = 16; o; o >>= 1)
            acc += __shfl_down_sync(0xffffffffu, acc, o);
        if ((t & 31) == 0) red[t >> 5] = acc;
        __syncthreads();
        if (t == 0) {
            float s = b4[0];
            #pragma unroll
            for (int w = 0; w < 8; w++) s += red[w];
            g_c = s;
        }
        return;
    }
    int warp = (blockIdx.x * blockDim.x + threadIdx.x) >> 5;
    int lane = threadIdx.x & 31;
    if (warp >= 2 * D) return;
    const float4* row = (const float4*)W1 + (size_t)warp * 256;  // 1024/4
    const float4* v4  = (const float4*)g_v2;
    float acc = 0.f;
    #pragma unroll
    for (int j = lane; j < 256; j += 32) {
        float4 a = row[j];
        float4 b = v4[j];
        acc = fmaf(a.x, b.x, acc);
        acc = fmaf(a.y, b.y, acc);
        acc = fmaf(a.z, b.z, acc);
        acc = fmaf(a.w, b.w, acc);
    }
    #pragma unroll
    for (int o = 16; o; o >>= 1)
        acc += __shfl_down_sync(0xffffffffu, acc, o);
    if (lane == 0) g_v1[warp] = acc;
}

// Warp-per-entity: stream the 901-float feature row once (coalesced 128B/iter),
// accumulate both half-dots simultaneously.
__global__ void k_scores(const float* __restrict__ feat) {
    int warp = (blockIdx.x * blockDim.x + threadIdx.x) >> 5;
    int lane = threadIdx.x & 31;
    if (warp >= N_ENT) return;
    const float* row = feat + (size_t)warp * D;
    float s1 = 0.f, s2 = 0.f;
    #pragma unroll 4
    for (int j = lane; j < D; j += 32) {
        float f = row[j];
        s1 = fmaf(f, g_v1[j], s1);
        s2 = fmaf(f, g_v1[D + j], s2);
    }
    #pragma unroll
    for (int o = 16; o; o >>= 1) {
        s1 += __shfl_down_sync(0xffffffffu, s1, o);
        s2 += __shfl_down_sync(0xffffffffu, s2, o);
    }
    if (lane == 0) {
        g_s[2 * warp]     = s1;
        g_s[2 * warp + 1] = s2;
    }
}

// Gather + sigmoid. Train pairs first (100000), then test (25000).
__global__ void k_out(const int* __restrict__ tr, const int* __restrict__ te,
                      float* __restrict__ out) {
    int k = blockIdx.x * blockDim.x + threadIdx.x;
    if (k >= B_TR + B_TE) return;
    int a, b;
    if (k < B_TR) { a = tr[2 * k];                 b = tr[2 * k + 1]; }
    else          { int m = k - B_TR; a = te[2 * m]; b = te[2 * m + 1]; }
    float z = g_s[2 * a] + g_s[2 * b + 1] + g_c;
    out[k] = 1.0f / (1.0f + __expf(-z));
}

extern "C" void kernel_launch(void* const* d_in, const int* in_sizes, int n_in,
                              void* d_out, int out_size) {
    const float* feature = (const float*)d_in[0];   // [20000, 901]
    const float* W1      = (const float*)d_in[1];   // [1802, 1024]
    const float* b1      = (const float*)d_in[2];   // [1024]
    const float* W2      = (const float*)d_in[3];   // [1024, 512]
    const float* b2      = (const float*)d_in[4];   // [512]
    const float* W3      = (const float*)d_in[5];   // [512, 64]
    const float* b3      = (const float*)d_in[6];   // [64]
    const float* W4      = (const float*)d_in[7];   // [64, 1]
    const float* b4      = (const float*)d_in[8];   // [1]
    const int*   tr      = (const int*)d_in[9];     // [100000, 2]
    const int*   te      = (const int*)d_in[10];    // [25000, 2]
    float*       out     = (float*)d_out;

    float *p_v3, *p_v2;
    cudaGetSymbolAddress((void**)&p_v3, g_v3);
    cudaGetSymbolAddress((void**)&p_v2, g_v2);

    const int TPB = 256;  // 8 warps/block
    // v3 = W3 @ v4   (512 rows, 64 cols -> cols4=16)
    k_matvec<<<(512 + 7) / 8, TPB>>>(W3, W4, p_v3, 512, 16);
    // v2 = W2 @ v3   (1024 rows, 512 cols -> cols4=128)
    k_matvec<<<(1024 + 7) / 8, TPB>>>(W2, p_v3, p_v2, 1024, 128);
    // v1 = W1 @ v2 (1802 rows) + fused bias constant (last block)
    k_v1_bias<<<(2 * D + 7) / 8 + 1, TPB>>>(W1, b1, b2, b3, b4, W4);
    // per-entity scores (20000 warps)
    k_scores<<<(N_ENT + 7) / 8, TPB>>>(feature);
    // final gather + sigmoid
    k_out<<<(B_TR + B_TE + TPB - 1) / TPB, TPB>>>(tr, te, out);
}